// round 11
// baseline (speedup 1.0000x reference)
#include <cuda_runtime.h>
#include <cuda_bf16.h>
#include <math.h>

#define BB 16
#define TT 1024
#define VV 4096
#define PP 100
#define LL 128

// scratch (allocation-free rule: __device__ globals)
__device__ unsigned g_map[BB * VV];                       // per-b vocab -> minpos
__device__ unsigned char g_ctok[BB * PP * TT + 64];       // compacted token ids (u8)
__device__ int g_clen[BB * PP];
__device__ float g_scores[BB * PP];
__device__ float g_wers[BB * PP];
__device__ unsigned g_done;

// ---------------------------------------------------------------------------
// Kernel A1: wide clear of the vocab map (+ done counter).
// ---------------------------------------------------------------------------
__global__ void __launch_bounds__(128) clear_kernel()
{
    const unsigned idx = blockIdx.x * 128u + threadIdx.x;
    uint4* mp = (uint4*)g_map;
    const uint4 f = make_uint4(~0u, ~0u, ~0u, ~0u);
    for (unsigned i = idx; i < (BB * VV) / 4; i += gridDim.x * 128u) mp[i] = f;
    if (idx == 0) g_done = 0;
}

// ---------------------------------------------------------------------------
// Kernel A2: map[b][c] = min label position of char c. id(c) = map[c]+1
// (wraps to 0 for chars not in the label).
// ---------------------------------------------------------------------------
__global__ void __launch_bounds__(128) scatter_kernel(
    const int* __restrict__ labels,
    const int* __restrict__ llen)
{
    const int b = blockIdx.x, tid = threadIdx.x;
    if (tid < llen[b])
        atomicMin(&g_map[(size_t)b * VV + labels[b * LL + tid]], (unsigned)tid);
}

// ---------------------------------------------------------------------------
// Kernel B: CTC-collapse + remap to u8 ids. One block per (b,p).
// valid = tok!=0 && tok!=raw_prev && t<len.
// ---------------------------------------------------------------------------
__global__ void __launch_bounds__(128) compact_kernel(
    const int* __restrict__ paths,
    const int* __restrict__ elen)
{
    const int bp = blockIdx.x;
    const int b  = bp / PP;
    const int len = elen[b];
    const int* pp = paths + (size_t)bp * TT;
    const unsigned* map = g_map + (size_t)b * VV;
    const int tid = threadIdx.x;
    const int t0 = tid * 8;

    int4 A = *(const int4*)(pp + t0);
    int4 Bv = *(const int4*)(pp + t0 + 4);
    int tok[8] = {A.x, A.y, A.z, A.w, Bv.x, Bv.y, Bv.z, Bv.w};
    const int prev0 = (t0 == 0) ? -1 : __ldg(pp + t0 - 1);

    unsigned char id[8];
    #pragma unroll
    for (int i = 0; i < 8; ++i)
        id[i] = (unsigned char)(__ldg(map + tok[i]) + 1u);   // 0 if not in label

    unsigned flags = 0;
    int cnt = 0;
    #pragma unroll
    for (int i = 0; i < 8; ++i) {
        int pr = (i == 0) ? prev0 : tok[i - 1];
        int v = ((t0 + i) < len) & (tok[i] != 0) & (tok[i] != pr);
        flags |= (unsigned)v << i;
        cnt += v;
    }

    const int lane = tid & 31, w = tid >> 5;
    int inc = cnt;
    #pragma unroll
    for (int o = 1; o < 32; o <<= 1) {
        int nn = __shfl_up_sync(0xffffffffu, inc, o);
        if (lane >= o) inc += nn;
    }
    __shared__ int wtot[4];
    if (lane == 31) wtot[w] = inc;
    __syncthreads();
    int wbase = 0;
    #pragma unroll
    for (int i = 0; i < 4; ++i) wbase += (i < w) ? wtot[i] : 0;
    int base = wbase + inc - cnt;

    unsigned char* out = g_ctok + (size_t)bp * TT;
    #pragma unroll
    for (int i = 0; i < 8; ++i)
        if ((flags >> i) & 1u) out[base++] = id[i];
    __syncthreads();
    if (tid == 0) g_clen[bp] = wtot[0] + wtot[1] + wtot[2] + wtot[3];
}

// ---------------------------------------------------------------------------
// Fused kernel: blocks 0..15 = edit distance, rest = scores; last finishing
// block runs the finalize reduction.
// ---------------------------------------------------------------------------
__device__ __forceinline__ void scores_body(
    int bp, const float* __restrict__ em, const int* __restrict__ elen,
    const int* __restrict__ paths, char* smem_raw)
{
    const int b   = bp / PP;
    const int len = elen[b];
    const int* pp = paths + (size_t)bp * TT;
    const float* eb = em + (size_t)b * TT * VV;
    const int tid = threadIdx.x;
    const int t0 = tid * 8;

    int4 A = *(const int4*)(pp + t0);
    int4 Bv = *(const int4*)(pp + t0 + 4);
    int tok[8] = {A.x, A.y, A.z, A.w, Bv.x, Bv.y, Bv.z, Bv.w};

    float a0 = 0.f, a1 = 0.f, a2 = 0.f, a3 = 0.f;
    #pragma unroll
    for (int i = 0; i < 8; i += 4) {
        if (t0 + i + 0 < len) a0 += __ldg(eb + (size_t)(t0 + i + 0) * VV + tok[i + 0]);
        if (t0 + i + 1 < len) a1 += __ldg(eb + (size_t)(t0 + i + 1) * VV + tok[i + 1]);
        if (t0 + i + 2 < len) a2 += __ldg(eb + (size_t)(t0 + i + 2) * VV + tok[i + 2]);
        if (t0 + i + 3 < len) a3 += __ldg(eb + (size_t)(t0 + i + 3) * VV + tok[i + 3]);
    }
    float acc = (a0 + a1) + (a2 + a3);
    #pragma unroll
    for (int o = 16; o; o >>= 1) acc += __shfl_down_sync(0xffffffffu, acc, o);
    float* ws = (float*)smem_raw;
    if ((tid & 31) == 0) ws[tid >> 5] = acc;
    __syncthreads();
    if (tid == 0) g_scores[bp] = ws[0] + ws[1] + ws[2] + ws[3];
    __syncthreads();
}

__device__ __forceinline__ void edit_body(
    int b, const int* __restrict__ labels, const int* __restrict__ llen,
    char* smem_raw)
{
    uint4* peq = (uint4*)smem_raw;   // 256 entries * 16B = 4KB
    const int tid = threadIdx.x;

    for (int i = tid; i < 256; i += 128) peq[i] = make_uint4(0, 0, 0, 0);
    __syncthreads();

    const int m = llen[b];                 // 64..128, uniform per block
    if (tid < m) {
        int c = labels[b * LL + tid];
        unsigned mp = __ldg(&g_map[(size_t)b * VV + c]);     // <= tid
        atomicOr(((unsigned*)&peq[mp + 1]) + (tid >> 5), 1u << (tid & 31));
    }
    __syncthreads();

    const int lane_p = (tid < PP) ? tid : (PP - 1);
    const int n = g_clen[b * PP + lane_p];
    const unsigned char* ct = g_ctok + (size_t)(b * PP + lane_p) * TT;

    int nW = n;
    #pragma unroll
    for (int o = 16; o; o >>= 1) nW = max(nW, __shfl_xor_sync(0xffffffffu, nW, o));
    const int nR = (nW + 7) & ~7;

    // 128-bit state in 4x u32
    unsigned VP0 = ~0u, VP1 = ~0u;
    unsigned VP2 = (m >= 96)  ? ~0u : ((m > 64) ? ((1u << (m - 64)) - 1u) : 0u);
    unsigned VP3 = (m >= 128) ? ~0u : ((m > 96) ? ((1u << (m - 96)) - 1u) : 0u);
    unsigned VN0 = 0u, VN1 = 0u, VN2 = 0u, VN3 = 0u;

    int score = m;
    const int wsel = (m - 1) >> 5;     // 1,2,3
    const int mbit = (m - 1) & 31;
    int nrem = n;

    // token pipeline (u8 ids, 8 per uint2)
    uint2 tv = *(const uint2*)(ct);
    uint2 tn = *(const uint2*)(ct + 8);
    uint4 E = peq[tv.x & 0xFFu];       // prefetch for token 0

    for (int j = 0; j < nR; j += 8) {
        const uint2 tf = *(const uint2*)(ct + j + 16);   // +64 global pad: safe
        const unsigned tw0 = tv.x, tw1 = tv.y;
        #pragma unroll
        for (int i = 0; i < 8; ++i) {
            const unsigned e0 = E.x, e1 = E.y, e2 = E.z, e3 = E.w;
            // prefetch next token's PEQ entry (one ahead)
            unsigned nid;
            if (i < 3)      nid = __byte_perm(tw0, 0, 0x4440 + (i + 1));
            else if (i < 7) nid = __byte_perm(tw1, 0, 0x4440 + (i - 3));
            else            nid = tn.x & 0xFFu;
            E = peq[nid];

            const unsigned a0 = e0 & VP0, a1 = e1 & VP1,
                           a2 = e2 & VP2, a3 = e3 & VP3;
            unsigned s0, s1, s2, s3;
            asm("add.cc.u32  %0, %4, %8;\n\t"
                "addc.cc.u32 %1, %5, %9;\n\t"
                "addc.cc.u32 %2, %6, %10;\n\t"
                "addc.u32    %3, %7, %11;"
                : "=r"(s0), "=r"(s1), "=r"(s2), "=r"(s3)
                : "r"(a0), "r"(a1), "r"(a2), "r"(a3),
                  "r"(VP0), "r"(VP1), "r"(VP2), "r"(VP3));

            const unsigned D00 = (s0 ^ VP0) | e0 | VN0;
            const unsigned D01 = (s1 ^ VP1) | e1 | VN1;
            const unsigned D02 = (s2 ^ VP2) | e2 | VN2;
            const unsigned D03 = (s3 ^ VP3) | e3 | VN3;

            const unsigned HP0 = VN0 | ~(D00 | VP0);
            const unsigned HP1 = VN1 | ~(D01 | VP1);
            const unsigned HP2 = VN2 | ~(D02 | VP2);
            const unsigned HP3 = VN3 | ~(D03 | VP3);
            const unsigned HN0 = VP0 & D00;
            const unsigned HN1 = VP1 & D01;
            const unsigned HN2 = VP2 & D02;
            const unsigned HN3 = VP3 & D03;

            const unsigned HPw = (wsel == 3) ? HP3 : ((wsel == 2) ? HP2 : HP1);
            const unsigned HNw = (wsel == 3) ? HN3 : ((wsel == 2) ? HN2 : HN1);
            const int d = (int)((HPw >> mbit) & 1u) - (int)((HNw >> mbit) & 1u);
            score += (nrem > 0) ? d : 0;
            --nrem;

            // 128-bit << 1 via independent funnel shifts (depth 1)
            const unsigned HPs0 = (HP0 << 1) | 1u;
            const unsigned HPs1 = __funnelshift_l(HP0, HP1, 1);
            const unsigned HPs2 = __funnelshift_l(HP1, HP2, 1);
            const unsigned HPs3 = __funnelshift_l(HP2, HP3, 1);
            const unsigned HNs0 = HN0 << 1;
            const unsigned HNs1 = __funnelshift_l(HN0, HN1, 1);
            const unsigned HNs2 = __funnelshift_l(HN1, HN2, 1);
            const unsigned HNs3 = __funnelshift_l(HN2, HN3, 1);

            VP0 = HNs0 | ~(D00 | HPs0);
            VP1 = HNs1 | ~(D01 | HPs1);
            VP2 = HNs2 | ~(D02 | HPs2);
            VP3 = HNs3 | ~(D03 | HPs3);
            VN0 = D00 & HPs0;
            VN1 = D01 & HPs1;
            VN2 = D02 & HPs2;
            VN3 = D03 & HPs3;
        }
        tv = tn; tn = tf;
    }
    if (tid < PP) g_wers[b * PP + tid] = (float)score;
    __syncthreads();
}

__device__ __forceinline__ void finalize_body(float* out, char* smem_raw)
{
    float* red = (float*)smem_raw;
    const int tid = threadIdx.x;
    float total = 0.f;
    __threadfence();

    for (int b = 0; b < BB; ++b) {
        float s = (tid < PP) ? g_scores[b * PP + tid] : -3.0e38f;
        red[tid] = s; __syncthreads();
        #pragma unroll
        for (int o = 64; o; o >>= 1) {
            if (tid < o) red[tid] = fmaxf(red[tid], red[tid + o]);
            __syncthreads();
        }
        const float mx = red[0];
        __syncthreads();

        const float e  = (tid < PP) ? expf(s - mx) : 0.f;
        const float ew = (tid < PP) ? e * g_wers[b * PP + tid] : 0.f;

        red[tid] = e; __syncthreads();
        #pragma unroll
        for (int o = 64; o; o >>= 1) {
            if (tid < o) red[tid] += red[tid + o];
            __syncthreads();
        }
        const float Z = red[0];
        __syncthreads();

        red[tid] = ew; __syncthreads();
        #pragma unroll
        for (int o = 64; o; o >>= 1) {
            if (tid < o) red[tid] += red[tid + o];
            __syncthreads();
        }
        const float S = red[0];
        __syncthreads();

        total += S / Z;
    }
    if (tid == 0) out[0] = total;
}

__global__ void __launch_bounds__(128) fused_kernel(
    const float* __restrict__ em,
    const int* __restrict__ elen,
    const int* __restrict__ paths,
    const int* __restrict__ labels,
    const int* __restrict__ llen,
    float* __restrict__ out)
{
    extern __shared__ char smem_raw[];
    __shared__ unsigned s_rank;

    if (blockIdx.x < BB)
        edit_body(blockIdx.x, labels, llen, smem_raw);
    else
        scores_body(blockIdx.x - BB, em, elen, paths, smem_raw);

    if (threadIdx.x == 0) {
        __threadfence();
        s_rank = atomicAdd(&g_done, 1u);
    }
    __syncthreads();
    if (s_rank == (unsigned)(BB + BB * PP - 1))
        finalize_body(out, smem_raw);
}

// ---------------------------------------------------------------------------
extern "C" void kernel_launch(void* const* d_in, const int* in_sizes, int n_in,
                              void* d_out, int out_size)
{
    const float* em     = (const float*)d_in[0];  // (B,T,V) f32
    const int*   elen   = (const int*)  d_in[1];  // (B,)
    const int*   labels = (const int*)  d_in[2];  // (B,L)
    const int*   llen   = (const int*)  d_in[3];  // (B,)
    const int*   paths  = (const int*)  d_in[4];  // (B,P,T)

    clear_kernel<<<256, 128>>>();
    scatter_kernel<<<BB, 128>>>(labels, llen);
    compact_kernel<<<BB * PP, 128>>>(paths, elen);

    const int smem = 4096 + 512;   // peq (4KB) / reduction scratch
    fused_kernel<<<BB + BB * PP, 128, smem>>>(em, elen, paths, labels, llen,
                                              (float*)d_out);
}

// round 12
// speedup vs baseline: 1.0587x; 1.0587x over previous
#include <cuda_runtime.h>
#include <cuda_bf16.h>
#include <math.h>

#define BB 16
#define TT 1024
#define VV 4096
#define PP 100
#define LL 128

// scratch (allocation-free rule: __device__ globals)
__device__ unsigned g_map[BB * VV];                       // per-b vocab -> minpos
__device__ unsigned char g_ctok[BB * PP * TT + 64];       // compacted token ids (u8)
__device__ int g_clen[BB * PP];
__device__ float g_scores[BB * PP];
__device__ float g_wers[BB * PP];
__device__ unsigned g_done;

// forced 3-input LOP3 with explicit immLut
#define LOP3_(r, a, b, c, imm)                                          \
    asm("lop3.b32 %0, %1, %2, %3, %4;"                                  \
        : "=r"(r) : "r"(a), "r"(b), "r"(c), "n"(imm))

// ---------------------------------------------------------------------------
// Kernel A1: wide clear of the vocab map (+ done counter).
// ---------------------------------------------------------------------------
__global__ void __launch_bounds__(128) clear_kernel()
{
    const unsigned idx = blockIdx.x * 128u + threadIdx.x;
    uint4* mp = (uint4*)g_map;
    const uint4 f = make_uint4(~0u, ~0u, ~0u, ~0u);
    for (unsigned i = idx; i < (BB * VV) / 4; i += gridDim.x * 128u) mp[i] = f;
    if (idx == 0) g_done = 0;
}

// ---------------------------------------------------------------------------
// Kernel A2: map[b][c] = min label position of char c. id(c) = map[c]+1
// (wraps to 0 for chars not in the label).
// ---------------------------------------------------------------------------
__global__ void __launch_bounds__(128) scatter_kernel(
    const int* __restrict__ labels,
    const int* __restrict__ llen)
{
    const int b = blockIdx.x, tid = threadIdx.x;
    if (tid < llen[b])
        atomicMin(&g_map[(size_t)b * VV + labels[b * LL + tid]], (unsigned)tid);
}

// ---------------------------------------------------------------------------
// Kernel B: CTC-collapse + remap to u8 ids. One block per (b,p).
// valid = tok!=0 && tok!=raw_prev && t<len.
// ---------------------------------------------------------------------------
__global__ void __launch_bounds__(128) compact_kernel(
    const int* __restrict__ paths,
    const int* __restrict__ elen)
{
    const int bp = blockIdx.x;
    const int b  = bp / PP;
    const int len = elen[b];
    const int* pp = paths + (size_t)bp * TT;
    const unsigned* map = g_map + (size_t)b * VV;
    const int tid = threadIdx.x;
    const int t0 = tid * 8;

    int4 A = *(const int4*)(pp + t0);
    int4 Bv = *(const int4*)(pp + t0 + 4);
    int tok[8] = {A.x, A.y, A.z, A.w, Bv.x, Bv.y, Bv.z, Bv.w};
    const int prev0 = (t0 == 0) ? -1 : __ldg(pp + t0 - 1);

    unsigned char id[8];
    #pragma unroll
    for (int i = 0; i < 8; ++i)
        id[i] = (unsigned char)(__ldg(map + tok[i]) + 1u);   // 0 if not in label

    unsigned flags = 0;
    int cnt = 0;
    #pragma unroll
    for (int i = 0; i < 8; ++i) {
        int pr = (i == 0) ? prev0 : tok[i - 1];
        int v = ((t0 + i) < len) & (tok[i] != 0) & (tok[i] != pr);
        flags |= (unsigned)v << i;
        cnt += v;
    }

    const int lane = tid & 31, w = tid >> 5;
    int inc = cnt;
    #pragma unroll
    for (int o = 1; o < 32; o <<= 1) {
        int nn = __shfl_up_sync(0xffffffffu, inc, o);
        if (lane >= o) inc += nn;
    }
    __shared__ int wtot[4];
    if (lane == 31) wtot[w] = inc;
    __syncthreads();
    int wbase = 0;
    #pragma unroll
    for (int i = 0; i < 4; ++i) wbase += (i < w) ? wtot[i] : 0;
    int base = wbase + inc - cnt;

    unsigned char* out = g_ctok + (size_t)bp * TT;
    #pragma unroll
    for (int i = 0; i < 8; ++i)
        if ((flags >> i) & 1u) out[base++] = id[i];
    __syncthreads();
    if (tid == 0) g_clen[bp] = wtot[0] + wtot[1] + wtot[2] + wtot[3];
}

// ---------------------------------------------------------------------------
// Fused kernel: blocks 0..15 = edit distance, rest = scores; last finishing
// block runs the finalize reduction.
// ---------------------------------------------------------------------------
__device__ __forceinline__ void scores_body(
    int bp, const float* __restrict__ em, const int* __restrict__ elen,
    const int* __restrict__ paths, char* smem_raw)
{
    const int b   = bp / PP;
    const int len = elen[b];
    const int* pp = paths + (size_t)bp * TT;
    const float* eb = em + (size_t)b * TT * VV;
    const int tid = threadIdx.x;
    const int t0 = tid * 8;

    int4 A = *(const int4*)(pp + t0);
    int4 Bv = *(const int4*)(pp + t0 + 4);
    int tok[8] = {A.x, A.y, A.z, A.w, Bv.x, Bv.y, Bv.z, Bv.w};

    float a0 = 0.f, a1 = 0.f, a2 = 0.f, a3 = 0.f;
    #pragma unroll
    for (int i = 0; i < 8; i += 4) {
        if (t0 + i + 0 < len) a0 += __ldg(eb + (size_t)(t0 + i + 0) * VV + tok[i + 0]);
        if (t0 + i + 1 < len) a1 += __ldg(eb + (size_t)(t0 + i + 1) * VV + tok[i + 1]);
        if (t0 + i + 2 < len) a2 += __ldg(eb + (size_t)(t0 + i + 2) * VV + tok[i + 2]);
        if (t0 + i + 3 < len) a3 += __ldg(eb + (size_t)(t0 + i + 3) * VV + tok[i + 3]);
    }
    float acc = (a0 + a1) + (a2 + a3);
    #pragma unroll
    for (int o = 16; o; o >>= 1) acc += __shfl_down_sync(0xffffffffu, acc, o);
    float* ws = (float*)smem_raw;
    if ((tid & 31) == 0) ws[tid >> 5] = acc;
    __syncthreads();
    if (tid == 0) g_scores[bp] = ws[0] + ws[1] + ws[2] + ws[3];
    __syncthreads();
}

__device__ __forceinline__ void edit_body(
    int b, const int* __restrict__ labels, const int* __restrict__ llen,
    char* smem_raw)
{
    uint4* peq = (uint4*)smem_raw;   // 256 entries * 16B = 4KB
    const int tid = threadIdx.x;

    for (int i = tid; i < 256; i += 128) peq[i] = make_uint4(0, 0, 0, 0);
    __syncthreads();

    const int m = llen[b];                 // 64..128, uniform per block
    if (tid < m) {
        int c = labels[b * LL + tid];
        unsigned mp = __ldg(&g_map[(size_t)b * VV + c]);     // <= tid
        atomicOr(((unsigned*)&peq[mp + 1]) + (tid >> 5), 1u << (tid & 31));
    }
    __syncthreads();

    const int lane_p = (tid < PP) ? tid : (PP - 1);
    const int n = g_clen[b * PP + lane_p];
    const unsigned char* ct = g_ctok + (size_t)(b * PP + lane_p) * TT;

    int nW = n;
    #pragma unroll
    for (int o = 16; o; o >>= 1) nW = max(nW, __shfl_xor_sync(0xffffffffu, nW, o));
    const int nR = (nW + 15) & ~15;

    // 128-bit state in 4x u32 (m >= 64 always)
    unsigned VP0 = ~0u, VP1 = ~0u;
    unsigned VP2 = (m >= 96)  ? ~0u : ((m > 64) ? ((1u << (m - 64)) - 1u) : 0u);
    unsigned VP3 = (m >= 128) ? ~0u : ((m > 96) ? ((1u << (m - 96)) - 1u) : 0u);
    unsigned VN0 = 0u, VN1 = 0u, VN2 = 0u, VN3 = 0u;

    int score = m;
    const int wsel = (m - 1) >> 5;     // 1,2,3
    const int mbit = (m - 1) & 31;
    int nrem = n;

    // token window: tv = tokens[j..j+15]; depth-2 PEQ prefetch (E0/E1)
    uint4 tv = *(const uint4*)(ct);
    uint4 E0 = peq[tv.x & 0xFFu];
    uint4 E1 = peq[(tv.x >> 8) & 0xFFu];

    for (int j = 0; j < nR; j += 16) {
        const uint4 tn = *(const uint4*)(ct + j + 16);   // +64 global pad: safe
        const unsigned w0 = tv.x, w1 = tv.y, w2 = tv.z, w3 = tv.w;
        #pragma unroll
        for (int i = 0; i < 16; ++i) {
            const uint4 Ecur = (i & 1) ? E1 : E0;

            // prefetch PEQ entry for token i+2 (depth-2 double buffer)
            const int k = i + 2;
            unsigned nid;
            if (k < 4)       nid = __byte_perm(w0, 0, 0x4440 | k);
            else if (k < 8)  nid = __byte_perm(w1, 0, 0x4440 | (k - 4));
            else if (k < 12) nid = __byte_perm(w2, 0, 0x4440 | (k - 8));
            else if (k < 16) nid = __byte_perm(w3, 0, 0x4440 | (k - 12));
            else             nid = __byte_perm(tn.x, 0, 0x4440 | (k - 16));
            const uint4 Enew = peq[nid];
            if (i & 1) E1 = Enew; else E0 = Enew;

            const unsigned e0 = Ecur.x, e1 = Ecur.y, e2 = Ecur.z, e3 = Ecur.w;
            const unsigned a0 = e0 & VP0, a1 = e1 & VP1,
                           a2 = e2 & VP2, a3 = e3 & VP3;
            unsigned s0, s1, s2, s3;
            asm("add.cc.u32  %0, %4, %8;\n\t"
                "addc.cc.u32 %1, %5, %9;\n\t"
                "addc.cc.u32 %2, %6, %10;\n\t"
                "addc.u32    %3, %7, %11;"
                : "=r"(s0), "=r"(s1), "=r"(s2), "=r"(s3)
                : "r"(a0), "r"(a1), "r"(a2), "r"(a3),
                  "r"(VP0), "r"(VP1), "r"(VP2), "r"(VP3));

            // D = ((s^VP)|Eq) | VN   (X = 1-LOP3: lut 0xBE)
            unsigned X0, X1, X2, X3;
            LOP3_(X0, s0, VP0, e0, 0xBE);
            LOP3_(X1, s1, VP1, e1, 0xBE);
            LOP3_(X2, s2, VP2, e2, 0xBE);
            LOP3_(X3, s3, VP3, e3, 0xBE);
            const unsigned D00 = X0 | VN0;
            const unsigned D01 = X1 | VN1;
            const unsigned D02 = X2 | VN2;
            const unsigned D03 = X3 | VN3;

            // HP = VN | ~(D|VP)  (1 LOP3: lut 0xF1)
            unsigned HP0, HP1, HP2, HP3;
            LOP3_(HP0, VN0, D00, VP0, 0xF1);
            LOP3_(HP1, VN1, D01, VP1, 0xF1);
            LOP3_(HP2, VN2, D02, VP2, 0xF1);
            LOP3_(HP3, VN3, D03, VP3, 0xF1);
            const unsigned HN0 = VP0 & D00;
            const unsigned HN1 = VP1 & D01;
            const unsigned HN2 = VP2 & D02;
            const unsigned HN3 = VP3 & D03;

            const unsigned HPw = (wsel == 3) ? HP3 : ((wsel == 2) ? HP2 : HP1);
            const unsigned HNw = (wsel == 3) ? HN3 : ((wsel == 2) ? HN2 : HN1);
            const int d = (int)((HPw >> mbit) & 1u) - (int)((HNw >> mbit) & 1u);
            score += (nrem > 0) ? d : 0;
            --nrem;

            // 128-bit << 1 via independent funnel shifts (depth 1)
            const unsigned HPs0 = (HP0 << 1) | 1u;
            const unsigned HPs1 = __funnelshift_l(HP0, HP1, 1);
            const unsigned HPs2 = __funnelshift_l(HP1, HP2, 1);
            const unsigned HPs3 = __funnelshift_l(HP2, HP3, 1);
            const unsigned HNs0 = HN0 << 1;
            const unsigned HNs1 = __funnelshift_l(HN0, HN1, 1);
            const unsigned HNs2 = __funnelshift_l(HN1, HN2, 1);
            const unsigned HNs3 = __funnelshift_l(HN2, HN3, 1);

            // VP' = HNs | ~(D|HPs)  (1 LOP3: lut 0xF1); VN' = D & HPs
            LOP3_(VP0, HNs0, D00, HPs0, 0xF1);
            LOP3_(VP1, HNs1, D01, HPs1, 0xF1);
            LOP3_(VP2, HNs2, D02, HPs2, 0xF1);
            LOP3_(VP3, HNs3, D03, HPs3, 0xF1);
            VN0 = D00 & HPs0;
            VN1 = D01 & HPs1;
            VN2 = D02 & HPs2;
            VN3 = D03 & HPs3;
        }
        tv = tn;
    }
    if (tid < PP) g_wers[b * PP + tid] = (float)score;
    __syncthreads();
}

__device__ __forceinline__ void finalize_body(float* out, char* smem_raw)
{
    float* red = (float*)smem_raw;
    const int tid = threadIdx.x;
    float total = 0.f;
    __threadfence();

    for (int b = 0; b < BB; ++b) {
        float s = (tid < PP) ? g_scores[b * PP + tid] : -3.0e38f;
        red[tid] = s; __syncthreads();
        #pragma unroll
        for (int o = 64; o; o >>= 1) {
            if (tid < o) red[tid] = fmaxf(red[tid], red[tid + o]);
            __syncthreads();
        }
        const float mx = red[0];
        __syncthreads();

        const float e  = (tid < PP) ? expf(s - mx) : 0.f;
        const float ew = (tid < PP) ? e * g_wers[b * PP + tid] : 0.f;

        red[tid] = e; __syncthreads();
        #pragma unroll
        for (int o = 64; o; o >>= 1) {
            if (tid < o) red[tid] += red[tid + o];
            __syncthreads();
        }
        const float Z = red[0];
        __syncthreads();

        red[tid] = ew; __syncthreads();
        #pragma unroll
        for (int o = 64; o; o >>= 1) {
            if (tid < o) red[tid] += red[tid + o];
            __syncthreads();
        }
        const float S = red[0];
        __syncthreads();

        total += S / Z;
    }
    if (tid == 0) out[0] = total;
}

__global__ void __launch_bounds__(128, 1) fused_kernel(
    const float* __restrict__ em,
    const int* __restrict__ elen,
    const int* __restrict__ paths,
    const int* __restrict__ labels,
    const int* __restrict__ llen,
    float* __restrict__ out)
{
    extern __shared__ char smem_raw[];
    __shared__ unsigned s_rank;

    if (blockIdx.x < BB)
        edit_body(blockIdx.x, labels, llen, smem_raw);
    else
        scores_body(blockIdx.x - BB, em, elen, paths, smem_raw);

    if (threadIdx.x == 0) {
        __threadfence();
        s_rank = atomicAdd(&g_done, 1u);
    }
    __syncthreads();
    if (s_rank == (unsigned)(BB + BB * PP - 1))
        finalize_body(out, smem_raw);
}

// ---------------------------------------------------------------------------
extern "C" void kernel_launch(void* const* d_in, const int* in_sizes, int n_in,
                              void* d_out, int out_size)
{
    const float* em     = (const float*)d_in[0];  // (B,T,V) f32
    const int*   elen   = (const int*)  d_in[1];  // (B,)
    const int*   labels = (const int*)  d_in[2];  // (B,L)
    const int*   llen   = (const int*)  d_in[3];  // (B,)
    const int*   paths  = (const int*)  d_in[4];  // (B,P,T)

    clear_kernel<<<256, 128>>>();
    scatter_kernel<<<BB, 128>>>(labels, llen);
    compact_kernel<<<BB * PP, 128>>>(paths, elen);

    const int smem = 4096 + 512;   // peq (4KB) / reduction scratch
    fused_kernel<<<BB + BB * PP, 128, smem>>>(em, elen, paths, labels, llen,
                                              (float*)d_out);
}

// round 13
// speedup vs baseline: 1.2527x; 1.1833x over previous
#include <cuda_runtime.h>
#include <cuda_bf16.h>
#include <math.h>

#define BB 16
#define TT 1024
#define VV 4096
#define PP 100
#define LL 128
#define NEDIT 64          // 4 blocks per b, 32 paths per block (4 lanes/path)

// scratch (allocation-free rule: __device__ globals)
__device__ unsigned g_map[BB * VV];                       // per-b vocab -> minpos
__device__ unsigned char g_ctok[BB * PP * TT + 64];       // compacted token ids (u8)
__device__ int g_clen[BB * PP];
__device__ float g_scores[BB * PP];
__device__ float g_wers[BB * PP];
__device__ unsigned g_done;

// forced 3-input LOP3 with explicit immLut
#define LOP3_(r, a, b, c, imm)                                          \
    asm("lop3.b32 %0, %1, %2, %3, %4;"                                  \
        : "=r"(r) : "r"(a), "r"(b), "r"(c), "n"(imm))

// ---------------------------------------------------------------------------
// Kernel A1: wide clear of the vocab map (+ done counter).
// ---------------------------------------------------------------------------
__global__ void __launch_bounds__(128) clear_kernel()
{
    const unsigned idx = blockIdx.x * 128u + threadIdx.x;
    uint4* mp = (uint4*)g_map;
    const uint4 f = make_uint4(~0u, ~0u, ~0u, ~0u);
    for (unsigned i = idx; i < (BB * VV) / 4; i += gridDim.x * 128u) mp[i] = f;
    if (idx == 0) g_done = 0;
}

// ---------------------------------------------------------------------------
// Kernel A2: map[b][c] = min label position of char c. id(c) = map[c]+1
// (wraps to 0 for chars not in the label).
// ---------------------------------------------------------------------------
__global__ void __launch_bounds__(128) scatter_kernel(
    const int* __restrict__ labels,
    const int* __restrict__ llen)
{
    const int b = blockIdx.x, tid = threadIdx.x;
    if (tid < llen[b])
        atomicMin(&g_map[(size_t)b * VV + labels[b * LL + tid]], (unsigned)tid);
}

// ---------------------------------------------------------------------------
// Kernel B: CTC-collapse + remap to u8 ids. One block per (b,p).
// valid = tok!=0 && tok!=raw_prev && t<len.
// ---------------------------------------------------------------------------
__global__ void __launch_bounds__(128) compact_kernel(
    const int* __restrict__ paths,
    const int* __restrict__ elen)
{
    const int bp = blockIdx.x;
    const int b  = bp / PP;
    const int len = elen[b];
    const int* pp = paths + (size_t)bp * TT;
    const unsigned* map = g_map + (size_t)b * VV;
    const int tid = threadIdx.x;
    const int t0 = tid * 8;

    int4 A = *(const int4*)(pp + t0);
    int4 Bv = *(const int4*)(pp + t0 + 4);
    int tok[8] = {A.x, A.y, A.z, A.w, Bv.x, Bv.y, Bv.z, Bv.w};
    const int prev0 = (t0 == 0) ? -1 : __ldg(pp + t0 - 1);

    unsigned char id[8];
    #pragma unroll
    for (int i = 0; i < 8; ++i)
        id[i] = (unsigned char)(__ldg(map + tok[i]) + 1u);   // 0 if not in label

    unsigned flags = 0;
    int cnt = 0;
    #pragma unroll
    for (int i = 0; i < 8; ++i) {
        int pr = (i == 0) ? prev0 : tok[i - 1];
        int v = ((t0 + i) < len) & (tok[i] != 0) & (tok[i] != pr);
        flags |= (unsigned)v << i;
        cnt += v;
    }

    const int lane = tid & 31, w = tid >> 5;
    int inc = cnt;
    #pragma unroll
    for (int o = 1; o < 32; o <<= 1) {
        int nn = __shfl_up_sync(0xffffffffu, inc, o);
        if (lane >= o) inc += nn;
    }
    __shared__ int wtot[4];
    if (lane == 31) wtot[w] = inc;
    __syncthreads();
    int wbase = 0;
    #pragma unroll
    for (int i = 0; i < 4; ++i) wbase += (i < w) ? wtot[i] : 0;
    int base = wbase + inc - cnt;

    unsigned char* out = g_ctok + (size_t)bp * TT;
    #pragma unroll
    for (int i = 0; i < 8; ++i)
        if ((flags >> i) & 1u) out[base++] = id[i];
    __syncthreads();
    if (tid == 0) g_clen[bp] = wtot[0] + wtot[1] + wtot[2] + wtot[3];
}

// ---------------------------------------------------------------------------
// Skewed Myers: 4 lanes per path, lane w owns state word w, processes token
// t = wall_step - w. Inter-word carries travel lane w-1 -> w via one packed
// shfl_up(width=4) per step, consumed one wall-step later (off critical path).
// ---------------------------------------------------------------------------
__device__ __forceinline__ void build_win(
    int w, unsigned sh, unsigned Pl, uint4 B,
    unsigned& C0, unsigned& C1, unsigned& C2, unsigned& C3)
{
    if (w == 0) { C0 = B.x; C1 = B.y; C2 = B.z; C3 = B.w; }
    else {
        C0 = __funnelshift_r(Pl,  B.x, sh);
        C1 = __funnelshift_r(B.x, B.y, sh);
        C2 = __funnelshift_r(B.y, B.z, sh);
        C3 = __funnelshift_r(B.z, B.w, sh);
    }
}

template<bool GUARD>
__device__ __forceinline__ void edit_block16(
    const unsigned* __restrict__ peqw, int w, int base_t,
    int n, bool isSel, int mbit,
    unsigned C0, unsigned C1, unsigned C2, unsigned C3, unsigned Cn0,
    unsigned& VP, unsigned& VN, unsigned& Eq_a, unsigned& Eq_b,
    unsigned& msgOut, int& score,
    unsigned c_and, unsigned hp_or)
{
    unsigned Cw[4] = {C0, C1, C2, C3};
    #pragma unroll
    for (int i = 0; i < 16; ++i) {
        const unsigned Eq = (i & 1) ? Eq_b : Eq_a;
        // prefetch PEQ word for step i+2 (depth-2)
        const int k = i + 2;
        const unsigned idn = (k < 16)
            ? __byte_perm(Cw[k >> 2], 0, 0x4440 | (k & 3))
            : __byte_perm(Cn0, 0, 0x4440 | (k & 3));
        const unsigned Eqn = peqw[(idn << 2) + w];
        if (i & 1) Eq_b = Eqn; else Eq_a = Eqn;

        // message from lane w-1 (produced at previous wall-step, same token)
        const unsigned msgIn = __shfl_up_sync(0xffffffffu, msgOut, 1, 4);
        const unsigned cin  = msgIn & c_and;
        const unsigned hpin = ((msgIn >> 1) & c_and) | hp_or;
        const unsigned hnin = (msgIn >> 2) & c_and;

        const unsigned a = Eq & VP;
        const unsigned long long wide = (unsigned long long)a + VP + cin;
        const unsigned sum  = (unsigned)wide;
        const unsigned cout = (unsigned)(wide >> 32);
        unsigned X; LOP3_(X, sum, VP, Eq, 0xBE);   // (sum^VP)|Eq
        const unsigned D = X | VN;
        unsigned HP; LOP3_(HP, VN, D, VP, 0xF1);   // VN | ~(D|VP)
        const unsigned HN = VP & D;

        const int t = base_t + i;
        const int d = (int)((HP >> mbit) & 1u) - (int)((HN >> mbit) & 1u);
        score += (isSel & ((unsigned)t < (unsigned)n)) ? d : 0;

        msgOut = cout | (((HP >> 31) & 1u) << 1) | ((HN >> 31) << 2);

        const unsigned HPs = (HP << 1) | hpin;
        const unsigned HNs = (HN << 1) | hnin;
        unsigned nVP; LOP3_(nVP, HNs, D, HPs, 0xF1);
        const unsigned nVN = D & HPs;
        if (GUARD) {
            const bool act = (t >= 0);
            VP = act ? nVP : VP;
            VN = act ? nVN : VN;
        } else {
            VP = nVP; VN = nVN;
        }
    }
}

__device__ __forceinline__ void edit_body(
    int blk, const int* __restrict__ labels, const int* __restrict__ llen,
    char* smem_raw)
{
    unsigned* peqw = (unsigned*)smem_raw;    // 256 ids * 4 words = 4KB
    const int b = blk >> 2;
    const int pbase = (blk & 3) * 32;
    const int tid = threadIdx.x;

    for (int i = tid; i < 1024; i += 128) peqw[i] = 0u;
    __syncthreads();
    const int m = llen[b];                   // 64..128, uniform per b
    if (tid < m) {
        int c = labels[b * LL + tid];
        unsigned mp = __ldg(&g_map[(size_t)b * VV + c]);
        atomicOr(&peqw[((mp + 1) << 2) + (tid >> 5)], 1u << (tid & 31));
    }
    __syncthreads();

    const int w = tid & 3;                   // word index
    const int p_raw = pbase + (tid >> 2);    // path within b
    const int p = (p_raw < PP) ? p_raw : (PP - 1);
    const int gp = b * PP + p;
    const int n = g_clen[gp];
    const unsigned char* ct = g_ctok + (size_t)gp * TT;

    int nW = n;
    #pragma unroll
    for (int o = 16; o; o >>= 1) nW = max(nW, __shfl_xor_sync(0xffffffffu, nW, o));
    const int nWall = ((nW + 3) + 15) & ~15;

    unsigned VP;
    if (w < 2)      VP = ~0u;
    else if (w == 2) VP = (m >= 96)  ? ~0u : ((m > 64) ? ((1u << (m - 64)) - 1u) : 0u);
    else             VP = (m >= 128) ? ~0u : ((m > 96) ? ((1u << (m - 96)) - 1u) : 0u);
    unsigned VN = 0u;

    const int wsel = (m - 1) >> 5, mbit = (m - 1) & 31;
    const bool isSel = (w == wsel);
    const unsigned c_and = w ? 1u : 0u;
    const unsigned hp_or = w ? 0u : 1u;
    const unsigned sh = (unsigned)(32 - 8 * w);

    int score = 0;
    unsigned msgOut = 0;

    uint4 B  = *(const uint4*)(ct);
    uint4 Bn = *(const uint4*)(ct + 16);
    unsigned C0, C1, C2, C3;
    build_win(w, sh, 0u, B, C0, C1, C2, C3);
    unsigned Eq_a = peqw[(__byte_perm(C0, 0, 0x4440) << 2) + w];
    unsigned Eq_b = peqw[(__byte_perm(C0, 0, 0x4441) << 2) + w];

    // peeled first wall-block (lead-in guard: lanes w>0 idle for t<0)
    {
        uint4 Bf = *(const uint4*)(ct + 32);
        unsigned Cn0, Cn1, Cn2, Cn3;
        build_win(w, sh, B.w, Bn, Cn0, Cn1, Cn2, Cn3);
        edit_block16<true>(peqw, w, 0 - w, n, isSel, mbit,
                           C0, C1, C2, C3, Cn0,
                           VP, VN, Eq_a, Eq_b, msgOut, score, c_and, hp_or);
        C0 = Cn0; C1 = Cn1; C2 = Cn2; C3 = Cn3;
        B = Bn; Bn = Bf;
    }
    for (int J = 16; J < nWall; J += 16) {
        uint4 Bf = *(const uint4*)(ct + J + 32);   // within +64 global pad
        unsigned Cn0, Cn1, Cn2, Cn3;
        build_win(w, sh, B.w, Bn, Cn0, Cn1, Cn2, Cn3);
        edit_block16<false>(peqw, w, J - w, n, isSel, mbit,
                            C0, C1, C2, C3, Cn0,
                            VP, VN, Eq_a, Eq_b, msgOut, score, c_and, hp_or);
        C0 = Cn0; C1 = Cn1; C2 = Cn2; C3 = Cn3;
        B = Bn; Bn = Bf;
    }

    if (isSel && p_raw < PP)
        g_wers[b * PP + p_raw] = (float)(m + score);
    __syncthreads();
}

// ---------------------------------------------------------------------------
// Scores: log-softmax normalizer cancels in the per-b softmax over paths.
// ---------------------------------------------------------------------------
__device__ __forceinline__ void scores_body(
    int bp, const float* __restrict__ em, const int* __restrict__ elen,
    const int* __restrict__ paths, char* smem_raw)
{
    const int b   = bp / PP;
    const int len = elen[b];
    const int* pp = paths + (size_t)bp * TT;
    const float* eb = em + (size_t)b * TT * VV;
    const int tid = threadIdx.x;
    const int t0 = tid * 8;

    int4 A = *(const int4*)(pp + t0);
    int4 Bv = *(const int4*)(pp + t0 + 4);
    int tok[8] = {A.x, A.y, A.z, A.w, Bv.x, Bv.y, Bv.z, Bv.w};

    float a0 = 0.f, a1 = 0.f, a2 = 0.f, a3 = 0.f;
    #pragma unroll
    for (int i = 0; i < 8; i += 4) {
        if (t0 + i + 0 < len) a0 += __ldg(eb + (size_t)(t0 + i + 0) * VV + tok[i + 0]);
        if (t0 + i + 1 < len) a1 += __ldg(eb + (size_t)(t0 + i + 1) * VV + tok[i + 1]);
        if (t0 + i + 2 < len) a2 += __ldg(eb + (size_t)(t0 + i + 2) * VV + tok[i + 2]);
        if (t0 + i + 3 < len) a3 += __ldg(eb + (size_t)(t0 + i + 3) * VV + tok[i + 3]);
    }
    float acc = (a0 + a1) + (a2 + a3);
    #pragma unroll
    for (int o = 16; o; o >>= 1) acc += __shfl_down_sync(0xffffffffu, acc, o);
    float* ws = (float*)smem_raw;
    if ((tid & 31) == 0) ws[tid >> 5] = acc;
    __syncthreads();
    if (tid == 0) g_scores[bp] = ws[0] + ws[1] + ws[2] + ws[3];
    __syncthreads();
}

__device__ __forceinline__ void finalize_body(float* out, char* smem_raw)
{
    float* red = (float*)smem_raw;
    const int tid = threadIdx.x;
    float total = 0.f;
    __threadfence();

    for (int b = 0; b < BB; ++b) {
        float s = (tid < PP) ? g_scores[b * PP + tid] : -3.0e38f;
        red[tid] = s; __syncthreads();
        #pragma unroll
        for (int o = 64; o; o >>= 1) {
            if (tid < o) red[tid] = fmaxf(red[tid], red[tid + o]);
            __syncthreads();
        }
        const float mx = red[0];
        __syncthreads();

        const float e  = (tid < PP) ? expf(s - mx) : 0.f;
        const float ew = (tid < PP) ? e * g_wers[b * PP + tid] : 0.f;

        red[tid] = e; __syncthreads();
        #pragma unroll
        for (int o = 64; o; o >>= 1) {
            if (tid < o) red[tid] += red[tid + o];
            __syncthreads();
        }
        const float Z = red[0];
        __syncthreads();

        red[tid] = ew; __syncthreads();
        #pragma unroll
        for (int o = 64; o; o >>= 1) {
            if (tid < o) red[tid] += red[tid + o];
            __syncthreads();
        }
        const float S = red[0];
        __syncthreads();

        total += S / Z;
    }
    if (tid == 0) out[0] = total;
}

__global__ void __launch_bounds__(128) fused_kernel(
    const float* __restrict__ em,
    const int* __restrict__ elen,
    const int* __restrict__ paths,
    const int* __restrict__ labels,
    const int* __restrict__ llen,
    float* __restrict__ out)
{
    extern __shared__ char smem_raw[];
    __shared__ unsigned s_rank;

    if (blockIdx.x < NEDIT)
        edit_body(blockIdx.x, labels, llen, smem_raw);
    else
        scores_body(blockIdx.x - NEDIT, em, elen, paths, smem_raw);

    if (threadIdx.x == 0) {
        __threadfence();
        s_rank = atomicAdd(&g_done, 1u);
    }
    __syncthreads();
    if (s_rank == (unsigned)(NEDIT + BB * PP - 1))
        finalize_body(out, smem_raw);
}

// ---------------------------------------------------------------------------
extern "C" void kernel_launch(void* const* d_in, const int* in_sizes, int n_in,
                              void* d_out, int out_size)
{
    const float* em     = (const float*)d_in[0];  // (B,T,V) f32
    const int*   elen   = (const int*)  d_in[1];  // (B,)
    const int*   labels = (const int*)  d_in[2];  // (B,L)
    const int*   llen   = (const int*)  d_in[3];  // (B,)
    const int*   paths  = (const int*)  d_in[4];  // (B,P,T)

    clear_kernel<<<256, 128>>>();
    scatter_kernel<<<BB, 128>>>(labels, llen);
    compact_kernel<<<BB * PP, 128>>>(paths, elen);

    const int smem = 4096 + 512;   // peq (4KB) + reduction scratch
    fused_kernel<<<NEDIT + BB * PP, 128, smem>>>(em, elen, paths, labels, llen,
                                                 (float*)d_out);
}